// round 2
// baseline (speedup 1.0000x reference)
#include <cuda_runtime.h>
#include <cuda_bf16.h>

// SurvivalGeometryRegularizer:
//   out = sum_{i,j} relu(1 + r_i - r_j) * [t_i < t_j] * [e_i==1] / count
// Inputs (metadata order): z [8192*128] f32 (UNUSED), risk [8192] f32,
//                          time [8192] f32, event [8192] i32. Output: 1 f32.
//
// Strategy: sort all rows by time (deterministic bucket sort). For an event
// row at sorted index s, valid j's are the suffix (strictly greater time).
// count is computed exactly from suffix lengths; the pair kernel only
// accumulates relu(a_i - r_sorted[j]) over suffixes (no compares).

#define NB       8192
#define NBUCK    2048
#define MBLK     32          // mega kernel blocks (all resident -> safe spin barrier)
#define MTHR     256
#define JC       256         // j chunk
#define TI       256         // i tile (compacted events)
#define PGX      32          // NB/JC
#define PGY      32          // NB/TI
#define NPART    (PGX*PGY)

// ---- persistent device scratch (no cudaMalloc allowed) ----
__device__ int   g_hist[NBUCK];          // zero-init; reset by final_k
__device__ volatile int g_bar[4];        // barrier arrive counters (reset by final_k)
__device__ volatile int g_rel[4];        // barrier release flags  (reset by final_k)
__device__ float g_ts[NB];               // sorted time
__device__ float g_rs[NB];               // sorted risk
__device__ int   g_key[NB];              // (orig_idx<<1)|event, sorted alongside
__device__ int   g_bc[MBLK];             // per-block event counts
__device__ int   g_pcnt[MBLK];           // per-block partial of total count (int)
__device__ int   g_posC[NB];             // compacted: suffix start (8192 for pad)
__device__ float g_aC[NB];               // compacted: 1 + risk   (0 for pad)
__device__ int   g_E;
__device__ float g_part[NPART];

// ---------------------------------------------------------------------------
__device__ __forceinline__ void grid_barrier(int k) {
    __syncthreads();
    if (threadIdx.x == 0) {
        __threadfence();
        int v = atomicAdd((int*)&g_bar[k], 1);
        if (v == MBLK - 1) {
            g_rel[k] = 1;
            __threadfence();
        } else {
            while (g_rel[k] == 0) { }
            __threadfence();
        }
    }
    __syncthreads();
}

// exclusive block scan over 256 ints; returns exclusive prefix, *total = sum.
// uses swarp[0..9]; ends with __syncthreads (safe to reuse swarp after).
__device__ __forceinline__ int bscan256(int v, int* swarp, int* total) {
    const int lane = threadIdx.x & 31;
    const int w    = threadIdx.x >> 5;
    int incl = v;
#pragma unroll
    for (int o = 1; o < 32; o <<= 1) {
        int n = __shfl_up_sync(0xFFFFFFFFu, incl, o);
        if (lane >= o) incl += n;
    }
    if (lane == 31) swarp[w] = incl;
    __syncthreads();
    if (w == 0) {
        int ws = (lane < 8) ? swarp[lane] : 0;
        int wi = ws;
#pragma unroll
        for (int o = 1; o < 8; o <<= 1) {
            int n = __shfl_up_sync(0xFFFFFFFFu, wi, o);
            if (lane >= o) wi += n;
        }
        if (lane < 8) swarp[lane] = wi - ws;   // exclusive warp offsets
        if (lane == 7) swarp[8] = wi;          // grand total
    }
    __syncthreads();
    int excl = swarp[w] + (incl - v);
    *total = swarp[8];
    __syncthreads();
    return excl;
}

// ---------------------------------------------------------------------------
// Mega kernel: histogram -> scan -> scatter -> per-bucket sort -> pos/compact
// ---------------------------------------------------------------------------
__global__ __launch_bounds__(MTHR)
void mega_k(const float* __restrict__ risk,
            const float* __restrict__ tim,
            const int*   __restrict__ event) {
    __shared__ int s_off[NBUCK + 1];
    __shared__ int s_warp[10];
    __shared__ int s_misc[2];

    const int tid = threadIdx.x;
    const int gid = blockIdx.x * MTHR + tid;    // one element per thread

    // ---- A: load + histogram ticket ----
    const float t = tim[gid];
    const float r = risk[gid];
    const int   e = event[gid];
    int b = (int)(t * (float)NBUCK);
    if (b < 0) b = 0;
    if (b > NBUCK - 1) b = NBUCK - 1;
    const int ticket = atomicAdd(&g_hist[b], 1);

    grid_barrier(0);

    // ---- C: every block redundantly scans the full histogram ----
    {
        int h[8];
        const int base = tid * 8;
        int tsum = 0;
#pragma unroll
        for (int i = 0; i < 8; i++) { h[i] = g_hist[base + i]; tsum += h[i]; }
        int tot;
        int excl = bscan256(tsum, s_warp, &tot);
        int run = excl;
#pragma unroll
        for (int i = 0; i < 8; i++) { s_off[base + i] = run; run += h[i]; }
        if (tid == 0) s_off[NBUCK] = NB;
        __syncthreads();
    }

    // ---- D: scatter into bucketed order ----
    {
        const int p = s_off[b] + ticket;
        g_ts[p]  = t;
        g_rs[p]  = r;
        g_key[p] = (gid << 1) | e;
    }

    grid_barrier(1);

    // ---- F: per-bucket insertion sort by (t, key) -> deterministic order ----
    if (gid < NBUCK) {
        const int s0 = s_off[gid];
        const int s1 = s_off[gid + 1];
        for (int i = s0 + 1; i < s1; i++) {
            float kt = g_ts[i]; float kr = g_rs[i]; int kk = g_key[i];
            int j = i - 1;
            while (j >= s0 && (g_ts[j] > kt || (g_ts[j] == kt && g_key[j] > kk))) {
                g_ts[j + 1] = g_ts[j]; g_rs[j + 1] = g_rs[j]; g_key[j + 1] = g_key[j];
                j--;
            }
            g_ts[j + 1] = kt; g_rs[j + 1] = kr; g_key[j + 1] = kk;
        }
    }

    grid_barrier(2);

    // ---- H: tie-aware suffix pos + stable compaction of events ----
    const int s = gid;                     // sorted index
    const int es = g_key[s] & 1;
    int   pos = NB;
    float a   = 0.0f;
    if (es) {
        const float ts = g_ts[s];
        pos = s + 1;
        while (pos < NB && g_ts[pos] == ts) pos++;   // skip ties (strict <)
        a = 1.0f + g_rs[s];
    }
    int btot;
    const int loc = bscan256(es, s_warp, &btot);     // block-local compact index
    if (tid == 0) g_bc[blockIdx.x] = btot;
    int ctot;
    (void)bscan256(es ? (NB - pos) : 0, s_warp, &ctot);
    if (tid == 0) g_pcnt[blockIdx.x] = ctot;

    grid_barrier(3);

    // ---- J: global offsets, write compacted arrays + padding ----
    if (tid == 0) {
        int off = 0, E = 0;
#pragma unroll
        for (int bb = 0; bb < MBLK; bb++) {
            int c = g_bc[bb];
            if (bb < (int)blockIdx.x) off += c;
            E += c;
        }
        s_misc[0] = off; s_misc[1] = E;
    }
    __syncthreads();
    if (es) {
        const int p = s_misc[0] + loc;
        g_posC[p] = pos;
        g_aC[p]   = a;
    }
    const int padidx = s_misc[1] + gid;
    if (padidx < NB) { g_posC[padidx] = NB; g_aC[padidx] = 0.0f; }
    if (blockIdx.x == 0 && tid == 0) g_E = s_misc[1];
}

// ---------------------------------------------------------------------------
// Pair kernel: sum of relu(a_i - r_sorted[j]) over suffixes. No compares.
// ---------------------------------------------------------------------------
__global__ __launch_bounds__(TI)
void pairs_k() {
    __shared__ float sr[JC + 8];
    __shared__ float red[TI];

    const int tid  = threadIdx.x;
    const int bx   = blockIdx.x;           // j chunk
    const int by   = blockIdx.y;           // i tile
    const int pidx = by * PGX + bx;
    const int tile0 = by * TI;
    const int E    = g_E;

    if (tile0 >= E) { if (tid == 0) g_part[pidx] = 0.0f; return; }

    const int J0   = bx * JC;
    const int pmin = g_posC[tile0];        // smallest pos in tile (sorted)
    if (J0 + JC <= pmin) { if (tid == 0) g_part[pidx] = 0.0f; return; }

    // stage j chunk (sorted risks); pad with +1e30 so relu -> 0
    sr[tid] = g_rs[J0 + tid];
    if (tid < 8) sr[JC + tid] = 1.0e30f;
    __syncthreads();

    const int   i   = tile0 + tid;         // consecutive -> pos monotone in warp
    const int   pos = g_posC[i];
    const float a   = g_aC[i];
    int js = pos - J0;
    js = js < 0 ? 0 : (js > JC ? JC : js);

    const int lo = __shfl_sync(0xFFFFFFFFu, js, 0) & ~3;   // warp min, aligned
    const int hi = __shfl_sync(0xFFFFFFFFu, js, 31);       // warp max

    float s0 = 0.f, s1 = 0.f, s2 = 0.f, s3 = 0.f;

    // masked prefix: only a handful of iterations per warp
    int j = lo;
    for (; j < hi; j += 4) {
        const float4 rr = *(const float4*)(sr + j);
        float h0 = fmaxf(a - rr.x, 0.f);
        float h1 = fmaxf(a - rr.y, 0.f);
        float h2 = fmaxf(a - rr.z, 0.f);
        float h3 = fmaxf(a - rr.w, 0.f);
        if (j + 0 >= js) s0 += h0;
        if (j + 1 >= js) s1 += h1;
        if (j + 2 >= js) s2 += h2;
        if (j + 3 >= js) s3 += h3;
    }
    // clean main loop: warp-uniform j, broadcast LDS.128, no predicates
#pragma unroll 2
    for (; j < JC; j += 4) {
        const float4 rr = *(const float4*)(sr + j);
        s0 += fmaxf(a - rr.x, 0.f);
        s1 += fmaxf(a - rr.y, 0.f);
        s2 += fmaxf(a - rr.z, 0.f);
        s3 += fmaxf(a - rr.w, 0.f);
    }

    red[tid] = (s0 + s1) + (s2 + s3);
    __syncthreads();
#pragma unroll
    for (int st = TI / 2; st > 0; st >>= 1) {
        if (tid < st) red[tid] += red[tid + st];
        __syncthreads();
    }
    if (tid == 0) g_part[pidx] = red[0];
}

// ---------------------------------------------------------------------------
// Final: reduce partials, divide by exact count, reset scratch for next replay
// ---------------------------------------------------------------------------
__global__ __launch_bounds__(1024)
void final_k(float* __restrict__ out) {
    __shared__ float red[1024];
    __shared__ int   icnt[32];
    const int tid = threadIdx.x;

    red[tid] = g_part[tid];
    if (tid < 32) icnt[tid] = g_pcnt[tid];
    __syncthreads();
#pragma unroll
    for (int st = 512; st > 0; st >>= 1) {
        if (tid < st) red[tid] += red[tid + st];
        __syncthreads();
    }
    if (tid == 0) {
        long long cnt = 0;
#pragma unroll
        for (int b = 0; b < 32; b++) cnt += icnt[b];
        out[0] = (cnt > 0) ? (red[0] / (float)cnt) : 0.0f;
    }

    // reset persistent scratch for the next graph replay
    g_hist[tid]        = 0;
    g_hist[tid + 1024] = 0;
    if (tid < 4) { g_bar[tid] = 0; g_rel[tid] = 0; }
}

extern "C" void kernel_launch(void* const* d_in, const int* in_sizes, int n_in,
                              void* d_out, int out_size) {
    const float* risk  = (const float*)d_in[1];
    const float* tim   = (const float*)d_in[2];
    const int*   event = (const int*)d_in[3];
    float* out = (float*)d_out;

    mega_k<<<MBLK, MTHR>>>(risk, tim, event);
    pairs_k<<<dim3(PGX, PGY), TI>>>();
    final_k<<<1, 1024>>>(out);
}

// round 6
// speedup vs baseline: 1.3776x; 1.3776x over previous
#include <cuda_runtime.h>
#include <cuda_bf16.h>

// SurvivalGeometryRegularizer:
//   out = sum_{i,j} relu(1 + r_i - r_j) * [t_i < t_j] * [e_i==1] / count
// Inputs (metadata order): z (UNUSED), risk[8192] f32, time[8192] f32,
//                          event[8192] i32. Output: 1 f32.
//
// Single fused kernel, grid 1024 = 64 j-chunks x 16 i-slices:
//  - block (bx,by): j-chunk bx (128 j's), raw i-slice by (512 rows)
//  - in-block deterministic scan-compaction of event rows into smem
//    (tot <= 512 = 2*THR ALWAYS -> no dropped rows, unlike R3)
//  - inner loop: int-bit time compare + predicated accumulate,
//    float4 smem broadcasts
//  - last block reduces 1024 partials, divides by exact integer count,
//    resets the ticket (graph-replay safe)

#define NB    8192
#define THR   256
#define ISL   512             // raw i rows per block (tot <= 512 guaranteed)
#define JC    128             // j's per block
#define GX    (NB / JC)       // 64
#define GY    (NB / ISL)      // 16
#define NBLK  (GX * GY)       // 1024
#define PINF  0x7F800000      // +INF bits (times are finite, non-negative)

__device__ float g_sum[NBLK];
__device__ int   g_cnt[NBLK];
__device__ int   g_done;      // zero-init; reset by last block each run

// exclusive block-wide scan over 256 ints; returns exclusive prefix, *total.
__device__ __forceinline__ int bscan256(int v, int* swarp, int* total) {
    const int lane = threadIdx.x & 31;
    const int w    = threadIdx.x >> 5;
    int incl = v;
#pragma unroll
    for (int o = 1; o < 32; o <<= 1) {
        int n = __shfl_up_sync(0xFFFFFFFFu, incl, o);
        if (lane >= o) incl += n;
    }
    if (lane == 31) swarp[w] = incl;
    __syncthreads();
    if (w == 0) {
        int ws = (lane < 8) ? swarp[lane] : 0;
        int wi = ws;
#pragma unroll
        for (int o = 1; o < 8; o <<= 1) {
            int n = __shfl_up_sync(0xFFFFFFFFu, wi, o);
            if (lane >= o) wi += n;
        }
        if (lane < 8) swarp[lane] = wi - ws;   // exclusive warp offsets
        if (lane == 7) swarp[8] = wi;          // grand total
    }
    __syncthreads();
    const int excl = swarp[w] + (incl - v);
    *total = swarp[8];
    __syncthreads();
    return excl;
}

__global__ __launch_bounds__(THR)
void fused_k(const float* __restrict__ risk,
             const float* __restrict__ tim,
             const int*   __restrict__ event,
             float* __restrict__ out) {
    __shared__ float s_tj[JC], s_rj[JC];
    __shared__ float s_ti[ISL + 2], s_ai[ISL + 2];
    __shared__ int   s_warp[10];
    __shared__ float s_redf[THR];
    __shared__ int   s_redi[THR];
    __shared__ int   s_last;

    const int tid = threadIdx.x;
    const int bx  = blockIdx.x & (GX - 1);
    const int by  = blockIdx.x >> 6;        // / GX, 0..15

    // ---- stage j chunk ----
    if (tid < JC) {
        s_tj[tid] = tim[bx * JC + tid];
        s_rj[tid] = risk[bx * JC + tid];
    }

    // ---- load raw i slice (2 rows/thread, coalesced) ----
    const int i0 = by * ISL;
    float tv[2], rv[2];
    int   ev[2];
#pragma unroll
    for (int p = 0; p < 2; p++) {
        const int idx = i0 + tid + p * THR;
        tv[p] = tim[idx];
        rv[p] = risk[idx];
        ev[p] = event[idx];
    }
    int tot;
    int pos = bscan256(ev[0] + ev[1], s_warp, &tot);

    // ---- deterministic compaction into shared (tot <= ISL = 2*THR) ----
#pragma unroll
    for (int p = 0; p < 2; p++) {
        if (ev[p]) {
            s_ti[pos] = tv[p];
            s_ai[pos] = 1.0f + rv[p];
            pos++;
        }
    }
    if (tid < 2) {                       // sentinel pad (never matches compare)
        s_ti[tot + tid] = __int_as_float(PINF);
        s_ai[tot + tid] = 0.0f;
    }
    __syncthreads();

    // ---- pair loop: 2 compacted i's per thread (covers tot fully) ----
    float sum = 0.0f;
    int   cnt = 0;
    const int c0 = 2 * tid;
    if (c0 < tot) {
        const int   tb0 = __float_as_int(s_ti[c0]);
        const int   tb1 = __float_as_int(s_ti[c0 + 1]);
        const float a0  = s_ai[c0];
        const float a1  = s_ai[c0 + 1];

#pragma unroll 8
        for (int j = 0; j < JC; j += 4) {
            const float4 t4 = *(const float4*)(s_tj + j);
            const float4 r4 = *(const float4*)(s_rj + j);
            {
                const int tjb = __float_as_int(t4.x);
                const float h0 = fmaxf(a0 - r4.x, 0.f);
                const float h1 = fmaxf(a1 - r4.x, 0.f);
                if (tb0 < tjb) { sum += h0; cnt++; }
                if (tb1 < tjb) { sum += h1; cnt++; }
            }
            {
                const int tjb = __float_as_int(t4.y);
                const float h0 = fmaxf(a0 - r4.y, 0.f);
                const float h1 = fmaxf(a1 - r4.y, 0.f);
                if (tb0 < tjb) { sum += h0; cnt++; }
                if (tb1 < tjb) { sum += h1; cnt++; }
            }
            {
                const int tjb = __float_as_int(t4.z);
                const float h0 = fmaxf(a0 - r4.z, 0.f);
                const float h1 = fmaxf(a1 - r4.z, 0.f);
                if (tb0 < tjb) { sum += h0; cnt++; }
                if (tb1 < tjb) { sum += h1; cnt++; }
            }
            {
                const int tjb = __float_as_int(t4.w);
                const float h0 = fmaxf(a0 - r4.w, 0.f);
                const float h1 = fmaxf(a1 - r4.w, 0.f);
                if (tb0 < tjb) { sum += h0; cnt++; }
                if (tb1 < tjb) { sum += h1; cnt++; }
            }
        }
    }

    // ---- deterministic block reduction ----
    s_redf[tid] = sum;
    s_redi[tid] = cnt;
    __syncthreads();
#pragma unroll
    for (int st = THR / 2; st > 0; st >>= 1) {
        if (tid < st) {
            s_redf[tid] += s_redf[tid + st];
            s_redi[tid] += s_redi[tid + st];
        }
        __syncthreads();
    }

    if (tid == 0) {
        g_sum[blockIdx.x] = s_redf[0];
        g_cnt[blockIdx.x] = s_redi[0];
        __threadfence();
        const int d = atomicAdd(&g_done, 1);
        s_last = (d == NBLK - 1);
    }
    __syncthreads();

    // ---- last block finishes: global reduce + divide + reset ticket ----
    if (s_last) {
        __threadfence();
        float fs = 0.0f;
        int   ic = 0;
#pragma unroll 4
        for (int k = tid; k < NBLK; k += THR) {   // fixed order -> deterministic
            fs += g_sum[k];
            ic += g_cnt[k];
        }
        s_redf[tid] = fs;
        s_redi[tid] = ic;
        __syncthreads();
#pragma unroll
        for (int st = THR / 2; st > 0; st >>= 1) {
            if (tid < st) {
                s_redf[tid] += s_redf[tid + st];
                s_redi[tid] += s_redi[tid + st];
            }
            __syncthreads();
        }
        if (tid == 0) {
            const int c = s_redi[0];
            out[0] = (c > 0) ? (s_redf[0] / (float)c) : 0.0f;
            g_done = 0;                 // reset for next graph replay
        }
    }
}

extern "C" void kernel_launch(void* const* d_in, const int* in_sizes, int n_in,
                              void* d_out, int out_size) {
    const float* risk  = (const float*)d_in[1];
    const float* tim   = (const float*)d_in[2];
    const int*   event = (const int*)d_in[3];
    float* out = (float*)d_out;

    fused_k<<<NBLK, THR>>>(risk, tim, event, out);
}